// round 6
// baseline (speedup 1.0000x reference)
#include <cuda_runtime.h>
#include <math.h>

#define NB 32
#define NC 256
#define NH 64
#define NW 64
#define MIP 8
#define EPS 1e-5f

// Intermediates (no allocation allowed -> device globals)
__device__ __align__(16) float g_s [NB * NC * 128];   // strip-pooled+BN : 4 MB
__device__ __align__(16) float g_y [NB * MIP * 128];  // conv1+BN+hswish : 128 KB
__device__ __align__(16) float g_ah[NB * NC * NH];    // 2 MB
__device__ __align__(16) float g_aw[NB * NC * NW];    // 2 MB

// ---------------------------------------------------------------------------
// Kernel 1: TWO (b,c) slices per block -> row/col means -> conv3+conv7 -> BN.
// 256 threads, 8 front-batched float4 loads per thread (MLP=8).
// ---------------------------------------------------------------------------
__global__ __launch_bounds__(256) void k_reduce_strip(
    const float* __restrict__ x,
    const float* __restrict__ sph_w3, const float* __restrict__ sph_w7,
    const float* __restrict__ sph_g,  const float* __restrict__ sph_b,
    const float* __restrict__ sph_m,  const float* __restrict__ sph_v,
    const float* __restrict__ spw_w3, const float* __restrict__ spw_w7,
    const float* __restrict__ spw_g,  const float* __restrict__ spw_b,
    const float* __restrict__ spw_m,  const float* __restrict__ spw_v)
{
    __shared__ __align__(16) float4 csum[2][256];  // per-slice column partials
    __shared__ float mrow[2][NH];
    __shared__ float mcol[2][NW];

    const int blk = blockIdx.x;        // 0..4095
    const int tid = threadIdx.x;       // 0..255
    const int grp = tid >> 4;          // 0..15 (row-group)
    const int w4  = tid & 15;          // float4 chunk along W

    // 8 independent float4 loads covering slices 2*blk and 2*blk+1
    const float4* x4 = (const float4*)(x + (size_t)blk * 2 * (NH * NW));
    float4 a0 = x4[tid];
    float4 a1 = x4[tid + 256];
    float4 a2 = x4[tid + 512];
    float4 a3 = x4[tid + 768];
    float4 b0 = x4[tid + 1024];
    float4 b1 = x4[tid + 1280];
    float4 b2 = x4[tid + 1536];
    float4 b3 = x4[tid + 1792];

    // Column partials
    float4 ca, cb;
    ca.x = a0.x + a1.x + a2.x + a3.x;  cb.x = b0.x + b1.x + b2.x + b3.x;
    ca.y = a0.y + a1.y + a2.y + a3.y;  cb.y = b0.y + b1.y + b2.y + b3.y;
    ca.z = a0.z + a1.z + a2.z + a3.z;  cb.z = b0.z + b1.z + b2.z + b3.z;
    ca.w = a0.w + a1.w + a2.w + a3.w;  cb.w = b0.w + b1.w + b2.w + b3.w;
    csum[0][tid] = ca;
    csum[1][tid] = cb;

    // Row chunk sums, reduce across 16 lanes sharing grp
    float r0 = a0.x + a0.y + a0.z + a0.w;
    float r1 = a1.x + a1.y + a1.z + a1.w;
    float r2 = a2.x + a2.y + a2.z + a2.w;
    float r3 = a3.x + a3.y + a3.z + a3.w;
    float s0 = b0.x + b0.y + b0.z + b0.w;
    float s1 = b1.x + b1.y + b1.z + b1.w;
    float s2 = b2.x + b2.y + b2.z + b2.w;
    float s3 = b3.x + b3.y + b3.z + b3.w;
#pragma unroll
    for (int m = 8; m >= 1; m >>= 1) {
        r0 += __shfl_xor_sync(0xffffffffu, r0, m);
        r1 += __shfl_xor_sync(0xffffffffu, r1, m);
        r2 += __shfl_xor_sync(0xffffffffu, r2, m);
        r3 += __shfl_xor_sync(0xffffffffu, r3, m);
        s0 += __shfl_xor_sync(0xffffffffu, s0, m);
        s1 += __shfl_xor_sync(0xffffffffu, s1, m);
        s2 += __shfl_xor_sync(0xffffffffu, s2, m);
        s3 += __shfl_xor_sync(0xffffffffu, s3, m);
    }
    if (w4 == 0) {
        mrow[0][grp]      = r0 * (1.f / 64.f);
        mrow[0][grp + 16] = r1 * (1.f / 64.f);
        mrow[0][grp + 32] = r2 * (1.f / 64.f);
        mrow[0][grp + 48] = r3 * (1.f / 64.f);
        mrow[1][grp]      = s0 * (1.f / 64.f);
        mrow[1][grp + 16] = s1 * (1.f / 64.f);
        mrow[1][grp + 32] = s2 * (1.f / 64.f);
        mrow[1][grp + 48] = s3 * (1.f / 64.f);
    }
    __syncthreads();

    // Column sums: threads 0..63 slice0, 64..127 slice1 (conflict-free)
    if (tid < 128) {
        const int sl  = tid >> 6;
        const int col = tid & 63;
        const float* cf = (const float*)csum[sl];
        float s = 0.f;
#pragma unroll
        for (int g = 0; g < 16; g++) s += cf[g * 64 + col];
        mcol[sl][col] = s * (1.f / 64.f);
    }
    __syncthreads();

    // Strip pool: all 256 threads. tid>>7 = slice, within: <64 h-strip, >=64 w.
    {
        const int sl  = tid >> 7;
        const int sub = tid & 127;
        const int l   = sub & 63;
        const int bc  = blk * 2 + sl;
        const int c   = bc & (NC - 1);

        const float* src; const float* w3; const float* w7;
        float g, bb, mm, vv; int off;
        if (sub < 64) {
            src = mrow[sl]; w3 = sph_w3 + c * 3; w7 = sph_w7 + c * 7;
            g = sph_g[c]; bb = sph_b[c]; mm = sph_m[c]; vv = sph_v[c]; off = 0;
        } else {
            src = mcol[sl]; w3 = spw_w3 + c * 3; w7 = spw_w7 + c * 7;
            g = spw_g[c]; bb = spw_b[c]; mm = spw_m[c]; vv = spw_v[c]; off = 64;
        }

        float acc = src[l];
#pragma unroll
        for (int j = 0; j < 3; j++) {
            int idx = l + j - 1;
            if (idx >= 0 && idx < 64) acc += src[idx] * w3[j];
        }
#pragma unroll
        for (int j = 0; j < 7; j++) {
            int idx = l + j - 3;
            if (idx >= 0 && idx < 64) acc += src[idx] * w7[j];
        }
        acc *= (1.f / 3.f);
        const float scale = g * rsqrtf(vv + EPS);
        g_s[(size_t)bc * 128 + off + l] = (acc - mm) * scale + bb;
    }
}

// ---------------------------------------------------------------------------
// Kernel 2: conv1 (C->MIP) + BN1 + hswish -> g_y.
// Grid = NB*4 (b, l-group of 32). Block 256 = 8 channel-groups x 32 l.
// ---------------------------------------------------------------------------
__global__ __launch_bounds__(256) void k_y(
    const float* __restrict__ conv1_w,
    const float* __restrict__ bn1_g, const float* __restrict__ bn1_b,
    const float* __restrict__ bn1_m, const float* __restrict__ bn1_v)
{
    __shared__ float w1s[MIP * NC];        // 8 KB
    __shared__ float part[8][MIP * 32];    // 8 KB

    const int b   = blockIdx.x >> 2;
    const int lg  = blockIdx.x & 3;
    const int tid = threadIdx.x;
    const int cg  = tid >> 5;              // channel group 0..7
    const int l   = tid & 31;              // l within group

#pragma unroll
    for (int i = 0; i < MIP; i++) w1s[tid + i * NC] = conv1_w[tid + i * NC];
    __syncthreads();

    float acc[MIP];
#pragma unroll
    for (int m = 0; m < MIP; m++) acc[m] = 0.f;

    const float* sp = g_s + (size_t)b * NC * 128 + (size_t)(cg * 32) * 128 + lg * 32 + l;
#pragma unroll 8
    for (int cc = 0; cc < 32; cc++) {
        const float v = sp[cc * 128];      // coalesced over l
#pragma unroll
        for (int m = 0; m < MIP; m++) acc[m] += w1s[m * NC + cg * 32 + cc] * v;
    }
#pragma unroll
    for (int m = 0; m < MIP; m++) part[cg][m * 32 + l] = acc[m];
    __syncthreads();

    // Reduce over the 8 channel-groups: thread tid handles (m = tid>>5, l = tid&31)
    {
        float s = 0.f;
#pragma unroll
        for (int g = 0; g < 8; g++) s += part[g][tid];
        const int m = tid >> 5;
        const float scale = bn1_g[m] * rsqrtf(bn1_v[m] + EPS);
        const float val   = (s - bn1_m[m]) * scale + bn1_b[m];
        g_y[(size_t)b * (MIP * 128) + m * 128 + lg * 32 + (tid & 31)] =
            val * fminf(fmaxf(val + 3.f, 0.f), 6.f) * (1.f / 6.f);
    }
}

// ---------------------------------------------------------------------------
// Kernel 2b: attention weights. One block per (b,c), 128 threads.
// ---------------------------------------------------------------------------
__global__ __launch_bounds__(128) void k_att(
    const float* __restrict__ convh_w, const float* __restrict__ convw_w)
{
    const int bc  = blockIdx.x;
    const int b   = bc >> 8;
    const int c   = bc & 255;
    const int tid = threadIdx.x;
    const int l   = tid & 63;
    const int off = (tid < 64) ? 0 : 64;

    const float* yb = g_y + (size_t)b * (MIP * 128) + off + l;
    const float* wp = ((tid < 64) ? convh_w : convw_w) + c * MIP;

    float s = 0.f;
#pragma unroll
    for (int m = 0; m < MIP; m++) s += wp[m] * yb[m * 128];
    const float a = 1.f / (1.f + __expf(-s));
    ((tid < 64) ? g_ah : g_aw)[bc * 64 + l] = a;
}

// ---------------------------------------------------------------------------
// Kernel 3: pure stream: out = x * ah[h] * aw[w]. Reverse order for L2 reuse.
// ---------------------------------------------------------------------------
__global__ __launch_bounds__(256) void k_apply(
    const float* __restrict__ x, float* __restrict__ out)
{
    const int bc  = (NB * NC - 1) - blockIdx.x;
    const int tid = threadIdx.x;

    const float4* x4  = (const float4*)(x   + (size_t)bc * (NH * NW));
    float4*       o4  = (float4*)      (out + (size_t)bc * (NH * NW));
    const float*  ahp = g_ah + bc * 64;
    const float4* awp = (const float4*)(g_aw + bc * 64);

#pragma unroll
    for (int i = 0; i < 4; i++) {
        const int f  = tid + i * 256;    // 0..1023
        const int h  = f >> 4;           // 0..63
        const int w4 = f & 15;           // 0..15
        const float4 xv = __ldg(&x4[f]);
        const float  a1 = __ldg(&ahp[h]);
        const float4 a2 = __ldg(&awp[w4]);
        float4 o;
        o.x = xv.x * a1 * a2.x;
        o.y = xv.y * a1 * a2.y;
        o.z = xv.z * a1 * a2.z;
        o.w = xv.w * a1 * a2.w;
        o4[f] = o;
    }
}

// ---------------------------------------------------------------------------
extern "C" void kernel_launch(void* const* d_in, const int* in_sizes, int n_in,
                              void* d_out, int out_size)
{
    const float* x       = (const float*)d_in[0];
    const float* sph_w3  = (const float*)d_in[1];
    const float* sph_w7  = (const float*)d_in[2];
    const float* sph_g   = (const float*)d_in[3];
    const float* sph_b   = (const float*)d_in[4];
    const float* sph_m   = (const float*)d_in[5];
    const float* sph_v   = (const float*)d_in[6];
    const float* spw_w3  = (const float*)d_in[7];
    const float* spw_w7  = (const float*)d_in[8];
    const float* spw_g   = (const float*)d_in[9];
    const float* spw_b   = (const float*)d_in[10];
    const float* spw_m   = (const float*)d_in[11];
    const float* spw_v   = (const float*)d_in[12];
    const float* conv1_w = (const float*)d_in[13];
    const float* bn1_g   = (const float*)d_in[14];
    const float* bn1_b   = (const float*)d_in[15];
    const float* bn1_m   = (const float*)d_in[16];
    const float* bn1_v   = (const float*)d_in[17];
    const float* convh_w = (const float*)d_in[18];
    const float* convw_w = (const float*)d_in[19];
    float* out = (float*)d_out;

    k_reduce_strip<<<NB * NC / 2, 256>>>(x,
        sph_w3, sph_w7, sph_g, sph_b, sph_m, sph_v,
        spw_w3, spw_w7, spw_g, spw_b, spw_m, spw_v);

    k_y<<<NB * 4, 256>>>(conv1_w, bn1_g, bn1_b, bn1_m, bn1_v);

    k_att<<<NB * NC, 128>>>(convh_w, convw_w);

    k_apply<<<NB * NC, 256>>>(x, out);
}

// round 7
// speedup vs baseline: 1.0770x; 1.0770x over previous
#include <cuda_runtime.h>
#include <math.h>

#define NB 32
#define NC 256
#define NH 64
#define NW 64
#define MIP 8
#define EPS 1e-5f

// Intermediates (no allocation allowed -> device globals)
__device__ __align__(16) float g_s [NB * NC * 128];   // strip-pooled+BN : 4 MB
__device__ __align__(16) float g_y [NB * MIP * 128];  // conv1+BN+hswish : 128 KB
__device__ __align__(16) float g_ah[NB * NC * NH];    // 2 MB
__device__ __align__(16) float g_aw[NB * NC * NW];    // 2 MB

// ---------------------------------------------------------------------------
// Kernel 1: per (b,c) slice -> row/col means -> depthwise conv3+conv7 -> BN
// (R4 version — proven fastest configuration)
// ---------------------------------------------------------------------------
__global__ __launch_bounds__(256) void k_reduce_strip(
    const float* __restrict__ x,
    const float* __restrict__ sph_w3, const float* __restrict__ sph_w7,
    const float* __restrict__ sph_g,  const float* __restrict__ sph_b,
    const float* __restrict__ sph_m,  const float* __restrict__ sph_v,
    const float* __restrict__ spw_w3, const float* __restrict__ spw_w7,
    const float* __restrict__ spw_g,  const float* __restrict__ spw_b,
    const float* __restrict__ spw_m,  const float* __restrict__ spw_v)
{
    __shared__ __align__(16) float4 csum[256];   // per-thread column partials
    __shared__ float  mrow[NH];
    __shared__ float  mcol[NW];

    const int bc  = blockIdx.x;       // b*256 + c
    const int c   = bc & (NC - 1);
    const int tid = threadIdx.x;      // 0..255
    const int grp = tid >> 4;         // 0..15 (row-group)
    const int w4  = tid & 15;         // which float4 along W

    const float4* x4 = (const float4*)(x + (size_t)bc * (NH * NW));
    float4 v0 = x4[tid];
    float4 v1 = x4[tid + 256];
    float4 v2 = x4[tid + 512];
    float4 v3 = x4[tid + 768];

    float4 cs;
    cs.x = v0.x + v1.x + v2.x + v3.x;
    cs.y = v0.y + v1.y + v2.y + v3.y;
    cs.z = v0.z + v1.z + v2.z + v3.z;
    cs.w = v0.w + v1.w + v2.w + v3.w;
    csum[tid] = cs;

    float r0 = v0.x + v0.y + v0.z + v0.w;
    float r1 = v1.x + v1.y + v1.z + v1.w;
    float r2 = v2.x + v2.y + v2.z + v2.w;
    float r3 = v3.x + v3.y + v3.z + v3.w;
#pragma unroll
    for (int m = 8; m >= 1; m >>= 1) {
        r0 += __shfl_xor_sync(0xffffffffu, r0, m);
        r1 += __shfl_xor_sync(0xffffffffu, r1, m);
        r2 += __shfl_xor_sync(0xffffffffu, r2, m);
        r3 += __shfl_xor_sync(0xffffffffu, r3, m);
    }
    if (w4 == 0) {
        mrow[grp]      = r0 * (1.f / 64.f);
        mrow[grp + 16] = r1 * (1.f / 64.f);
        mrow[grp + 32] = r2 * (1.f / 64.f);
        mrow[grp + 48] = r3 * (1.f / 64.f);
    }
    __syncthreads();

    if (tid < 64) {
        const float* cf = (const float*)csum;
        float s = 0.f;
#pragma unroll
        for (int g = 0; g < 16; g++) s += cf[g * 64 + tid];
        mcol[tid] = s * (1.f / 64.f);
    }
    __syncthreads();

    if (tid < 128) {
        const int l = tid & 63;
        const float* src; const float* w3; const float* w7;
        float g, bb, mm, vv; int off;
        if (tid < 64) {
            src = mrow; w3 = sph_w3 + c * 3; w7 = sph_w7 + c * 7;
            g = sph_g[c]; bb = sph_b[c]; mm = sph_m[c]; vv = sph_v[c]; off = 0;
        } else {
            src = mcol; w3 = spw_w3 + c * 3; w7 = spw_w7 + c * 7;
            g = spw_g[c]; bb = spw_b[c]; mm = spw_m[c]; vv = spw_v[c]; off = 64;
        }

        float acc = src[l];
#pragma unroll
        for (int j = 0; j < 3; j++) {
            int idx = l + j - 1;
            if (idx >= 0 && idx < 64) acc += src[idx] * w3[j];
        }
#pragma unroll
        for (int j = 0; j < 7; j++) {
            int idx = l + j - 3;
            if (idx >= 0 && idx < 64) acc += src[idx] * w7[j];
        }
        acc *= (1.f / 3.f);
        const float scale = g * rsqrtf(vv + EPS);
        g_s[(size_t)bc * 128 + off + l] = (acc - mm) * scale + bb;
    }
}

// ---------------------------------------------------------------------------
// Kernel 2: per batch: conv1 (C->MIP) + BN1 + hswish -> g_y.  (R4 version)
// ---------------------------------------------------------------------------
__global__ __launch_bounds__(256) void k_y(
    const float* __restrict__ conv1_w,
    const float* __restrict__ bn1_g, const float* __restrict__ bn1_b,
    const float* __restrict__ bn1_m, const float* __restrict__ bn1_v)
{
    __shared__ float w1s[MIP * NC];       // 8 KB
    __shared__ float part[2 * MIP * 128]; // 8 KB

    const int b    = blockIdx.x;
    const int tid  = threadIdx.x;
    const int half = tid >> 7;
    const int l    = tid & 127;

#pragma unroll
    for (int i = 0; i < MIP; i++) w1s[tid + i * NC] = conv1_w[tid + i * NC];
    __syncthreads();

    float acc[MIP];
#pragma unroll
    for (int m = 0; m < MIP; m++) acc[m] = 0.f;

    const float* sp = g_s + (size_t)b * NC * 128 + half * 128 * 128 + l;
#pragma unroll 4
    for (int cc = 0; cc < 128; cc++) {
        const float v = sp[(size_t)cc * 128];
#pragma unroll
        for (int m = 0; m < MIP; m++) acc[m] += w1s[m * NC + half * 128 + cc] * v;
    }
#pragma unroll
    for (int m = 0; m < MIP; m++) part[(half * MIP + m) * 128 + l] = acc[m];
    __syncthreads();

    if (tid < 128) {
#pragma unroll
        for (int m = 0; m < MIP; m++) {
            const float s2    = part[m * 128 + tid] + part[(MIP + m) * 128 + tid];
            const float scale = bn1_g[m] * rsqrtf(bn1_v[m] + EPS);
            const float val   = (s2 - bn1_m[m]) * scale + bn1_b[m];
            g_y[(size_t)b * (MIP * 128) + m * 128 + tid] =
                val * fminf(fmaxf(val + 3.f, 0.f), 6.f) * (1.f / 6.f);
        }
    }
}

// ---------------------------------------------------------------------------
// Kernel 2b: attention weights. One block per (b,c), 128 threads. (R4 version)
// ---------------------------------------------------------------------------
__global__ __launch_bounds__(128) void k_att(
    const float* __restrict__ convh_w, const float* __restrict__ convw_w)
{
    const int bc  = blockIdx.x;
    const int b   = bc >> 8;
    const int c   = bc & 255;
    const int tid = threadIdx.x;
    const int l   = tid & 63;
    const int off = (tid < 64) ? 0 : 64;

    const float* yb = g_y + (size_t)b * (MIP * 128) + off + l;
    const float* wp = ((tid < 64) ? convh_w : convw_w) + c * MIP;

    float s = 0.f;
#pragma unroll
    for (int m = 0; m < MIP; m++) s += wp[m] * yb[m * 128];
    const float a = 1.f / (1.f + __expf(-s));
    ((tid < 64) ? g_ah : g_aw)[bc * 64 + l] = a;
}

// ---------------------------------------------------------------------------
// Kernel 3: pure stream: out = x * ah[h] * aw[w]. Reverse order for L2 reuse.
// NEW: streaming stores (__stcs) — out is never re-read, keep L2 for x.
// ---------------------------------------------------------------------------
__global__ __launch_bounds__(256) void k_apply(
    const float* __restrict__ x, float* __restrict__ out)
{
    const int bc  = (NB * NC - 1) - blockIdx.x;
    const int tid = threadIdx.x;

    const float4* x4  = (const float4*)(x   + (size_t)bc * (NH * NW));
    float4*       o4  = (float4*)      (out + (size_t)bc * (NH * NW));
    const float*  ahp = g_ah + bc * 64;
    const float4* awp = (const float4*)(g_aw + bc * 64);

#pragma unroll
    for (int i = 0; i < 4; i++) {
        const int f  = tid + i * 256;    // 0..1023
        const int h  = f >> 4;           // 0..63
        const int w4 = f & 15;           // 0..15
        const float4 xv = __ldg(&x4[f]);
        const float  a1 = __ldg(&ahp[h]);
        const float4 a2 = __ldg(&awp[w4]);
        float4 o;
        o.x = xv.x * a1 * a2.x;
        o.y = xv.y * a1 * a2.y;
        o.z = xv.z * a1 * a2.z;
        o.w = xv.w * a1 * a2.w;
        __stcs(&o4[f], o);               // streaming store: evict-first in L2
    }
}

// ---------------------------------------------------------------------------
extern "C" void kernel_launch(void* const* d_in, const int* in_sizes, int n_in,
                              void* d_out, int out_size)
{
    const float* x       = (const float*)d_in[0];
    const float* sph_w3  = (const float*)d_in[1];
    const float* sph_w7  = (const float*)d_in[2];
    const float* sph_g   = (const float*)d_in[3];
    const float* sph_b   = (const float*)d_in[4];
    const float* sph_m   = (const float*)d_in[5];
    const float* sph_v   = (const float*)d_in[6];
    const float* spw_w3  = (const float*)d_in[7];
    const float* spw_w7  = (const float*)d_in[8];
    const float* spw_g   = (const float*)d_in[9];
    const float* spw_b   = (const float*)d_in[10];
    const float* spw_m   = (const float*)d_in[11];
    const float* spw_v   = (const float*)d_in[12];
    const float* conv1_w = (const float*)d_in[13];
    const float* bn1_g   = (const float*)d_in[14];
    const float* bn1_b   = (const float*)d_in[15];
    const float* bn1_m   = (const float*)d_in[16];
    const float* bn1_v   = (const float*)d_in[17];
    const float* convh_w = (const float*)d_in[18];
    const float* convw_w = (const float*)d_in[19];
    float* out = (float*)d_out;

    k_reduce_strip<<<NB * NC, 256>>>(x,
        sph_w3, sph_w7, sph_g, sph_b, sph_m, sph_v,
        spw_w3, spw_w7, spw_g, spw_b, spw_m, spw_v);

    k_y<<<NB, 256>>>(conv1_w, bn1_g, bn1_b, bn1_m, bn1_v);

    k_att<<<NB * NC, 128>>>(convh_w, convw_w);

    k_apply<<<NB * NC, 256>>>(x, out);
}

// round 9
// speedup vs baseline: 1.0787x; 1.0016x over previous
#include <cuda_runtime.h>
#include <math.h>

#define NB 32
#define NC 256
#define NH 64
#define NW 64
#define MIP 8
#define EPS 1e-5f

// Intermediates (no allocation allowed -> device globals)
__device__ __align__(16) float g_s [NB * NC * 128];   // strip-pooled+BN : 4 MB
__device__ __align__(16) float g_y [NB * MIP * 128];  // conv1+BN+hswish : 128 KB
__device__ __align__(16) float g_ah[NB * NC * NH];    // 2 MB
__device__ __align__(16) float g_aw[NB * NC * NW];    // 2 MB

// ---------------------------------------------------------------------------
// Kernel 1: per (b,c) slice -> row/col means -> depthwise conv3+conv7 -> BN.
// 128 threads, 8 front-batched float4 loads (MLP=8), short tail, 16 CTAs/SM.
// Same one-slice-per-block mapping as R4 (preserves L2 tail for k_apply).
// ---------------------------------------------------------------------------
__global__ __launch_bounds__(128) void k_reduce_strip(
    const float* __restrict__ x,
    const float* __restrict__ sph_w3, const float* __restrict__ sph_w7,
    const float* __restrict__ sph_g,  const float* __restrict__ sph_b,
    const float* __restrict__ sph_m,  const float* __restrict__ sph_v,
    const float* __restrict__ spw_w3, const float* __restrict__ spw_w7,
    const float* __restrict__ spw_g,  const float* __restrict__ spw_b,
    const float* __restrict__ spw_m,  const float* __restrict__ spw_v)
{
    __shared__ __align__(16) float4 csum[128];   // per-thread column partials (2 KB)
    __shared__ float  mrow[NH];
    __shared__ float  mcol[NW];

    const int bc  = blockIdx.x;       // b*256 + c
    const int c   = bc & (NC - 1);
    const int tid = threadIdx.x;      // 0..127
    const int grp = tid >> 4;         // 0..7 (row-group)
    const int w4  = tid & 15;         // float4 chunk along W

    // 8 front-batched float4 loads: f = tid + 128*i -> row h = grp + 8*i
    const float4* x4 = (const float4*)(x + (size_t)bc * (NH * NW));
    float4 v0 = x4[tid];
    float4 v1 = x4[tid + 128];
    float4 v2 = x4[tid + 256];
    float4 v3 = x4[tid + 384];
    float4 v4 = x4[tid + 512];
    float4 v5 = x4[tid + 640];
    float4 v6 = x4[tid + 768];
    float4 v7 = x4[tid + 896];

    // Column partials over this thread's 8 rows
    float4 cs;
    cs.x = (v0.x + v1.x) + (v2.x + v3.x) + ((v4.x + v5.x) + (v6.x + v7.x));
    cs.y = (v0.y + v1.y) + (v2.y + v3.y) + ((v4.y + v5.y) + (v6.y + v7.y));
    cs.z = (v0.z + v1.z) + (v2.z + v3.z) + ((v4.z + v5.z) + (v6.z + v7.z));
    cs.w = (v0.w + v1.w) + (v2.w + v3.w) + ((v4.w + v5.w) + (v6.w + v7.w));
    csum[tid] = cs;

    // Row chunk sums; reduce across the 16 lanes sharing grp (xor stays in half)
    float r0 = v0.x + v0.y + v0.z + v0.w;
    float r1 = v1.x + v1.y + v1.z + v1.w;
    float r2 = v2.x + v2.y + v2.z + v2.w;
    float r3 = v3.x + v3.y + v3.z + v3.w;
    float r4 = v4.x + v4.y + v4.z + v4.w;
    float r5 = v5.x + v5.y + v5.z + v5.w;
    float r6 = v6.x + v6.y + v6.z + v6.w;
    float r7 = v7.x + v7.y + v7.z + v7.w;
#pragma unroll
    for (int m = 8; m >= 1; m >>= 1) {
        r0 += __shfl_xor_sync(0xffffffffu, r0, m);
        r1 += __shfl_xor_sync(0xffffffffu, r1, m);
        r2 += __shfl_xor_sync(0xffffffffu, r2, m);
        r3 += __shfl_xor_sync(0xffffffffu, r3, m);
        r4 += __shfl_xor_sync(0xffffffffu, r4, m);
        r5 += __shfl_xor_sync(0xffffffffu, r5, m);
        r6 += __shfl_xor_sync(0xffffffffu, r6, m);
        r7 += __shfl_xor_sync(0xffffffffu, r7, m);
    }
    if (w4 == 0) {
        mrow[grp]      = r0 * (1.f / 64.f);
        mrow[grp + 8]  = r1 * (1.f / 64.f);
        mrow[grp + 16] = r2 * (1.f / 64.f);
        mrow[grp + 24] = r3 * (1.f / 64.f);
        mrow[grp + 32] = r4 * (1.f / 64.f);
        mrow[grp + 40] = r5 * (1.f / 64.f);
        mrow[grp + 48] = r6 * (1.f / 64.f);
        mrow[grp + 56] = r7 * (1.f / 64.f);
    }
    __syncthreads();

    // Column sums: thread w (<64) reduces column w over 8 row-groups.
    // float index g*64 + w -> consecutive across threads, conflict-free.
    if (tid < 64) {
        const float* cf = (const float*)csum;
        float s = 0.f;
#pragma unroll
        for (int g = 0; g < 8; g++) s += cf[g * 64 + tid];
        mcol[tid] = s * (1.f / 64.f);
    }
    __syncthreads();

    // Strip pool: (x + conv3(x) + conv7(x))/3, then BN. All 128 threads.
    {
        const int l = tid & 63;
        const float* src; const float* w3; const float* w7;
        float g, bb, mm, vv; int off;
        if (tid < 64) {
            src = mrow; w3 = sph_w3 + c * 3; w7 = sph_w7 + c * 7;
            g = sph_g[c]; bb = sph_b[c]; mm = sph_m[c]; vv = sph_v[c]; off = 0;
        } else {
            src = mcol; w3 = spw_w3 + c * 3; w7 = spw_w7 + c * 7;
            g = spw_g[c]; bb = spw_b[c]; mm = spw_m[c]; vv = spw_v[c]; off = 64;
        }

        float acc = src[l];
#pragma unroll
        for (int j = 0; j < 3; j++) {
            int idx = l + j - 1;
            if (idx >= 0 && idx < 64) acc += src[idx] * w3[j];
        }
#pragma unroll
        for (int j = 0; j < 7; j++) {
            int idx = l + j - 3;
            if (idx >= 0 && idx < 64) acc += src[idx] * w7[j];
        }
        acc *= (1.f / 3.f);
        const float scale = g * rsqrtf(vv + EPS);
        g_s[(size_t)bc * 128 + off + l] = (acc - mm) * scale + bb;
    }
}

// ---------------------------------------------------------------------------
// Kernel 2: per batch: conv1 (C->MIP) + BN1 + hswish -> g_y.  (R4 version)
// ---------------------------------------------------------------------------
__global__ __launch_bounds__(256) void k_y(
    const float* __restrict__ conv1_w,
    const float* __restrict__ bn1_g, const float* __restrict__ bn1_b,
    const float* __restrict__ bn1_m, const float* __restrict__ bn1_v)
{
    __shared__ float w1s[MIP * NC];       // 8 KB
    __shared__ float part[2 * MIP * 128]; // 8 KB

    const int b    = blockIdx.x;
    const int tid  = threadIdx.x;
    const int half = tid >> 7;
    const int l    = tid & 127;

#pragma unroll
    for (int i = 0; i < MIP; i++) w1s[tid + i * NC] = conv1_w[tid + i * NC];
    __syncthreads();

    float acc[MIP];
#pragma unroll
    for (int m = 0; m < MIP; m++) acc[m] = 0.f;

    const float* sp = g_s + (size_t)b * NC * 128 + half * 128 * 128 + l;
#pragma unroll 4
    for (int cc = 0; cc < 128; cc++) {
        const float v = sp[(size_t)cc * 128];
#pragma unroll
        for (int m = 0; m < MIP; m++) acc[m] += w1s[m * NC + half * 128 + cc] * v;
    }
#pragma unroll
    for (int m = 0; m < MIP; m++) part[(half * MIP + m) * 128 + l] = acc[m];
    __syncthreads();

    if (tid < 128) {
#pragma unroll
        for (int m = 0; m < MIP; m++) {
            const float s2    = part[m * 128 + tid] + part[(MIP + m) * 128 + tid];
            const float scale = bn1_g[m] * rsqrtf(bn1_v[m] + EPS);
            const float val   = (s2 - bn1_m[m]) * scale + bn1_b[m];
            g_y[(size_t)b * (MIP * 128) + m * 128 + tid] =
                val * fminf(fmaxf(val + 3.f, 0.f), 6.f) * (1.f / 6.f);
        }
    }
}

// ---------------------------------------------------------------------------
// Kernel 2b: attention weights. One block per (b,c), 128 threads. (R4 version)
// ---------------------------------------------------------------------------
__global__ __launch_bounds__(128) void k_att(
    const float* __restrict__ convh_w, const float* __restrict__ convw_w)
{
    const int bc  = blockIdx.x;
    const int b   = bc >> 8;
    const int c   = bc & 255;
    const int tid = threadIdx.x;
    const int l   = tid & 63;
    const int off = (tid < 64) ? 0 : 64;

    const float* yb = g_y + (size_t)b * (MIP * 128) + off + l;
    const float* wp = ((tid < 64) ? convh_w : convw_w) + c * MIP;

    float s = 0.f;
#pragma unroll
    for (int m = 0; m < MIP; m++) s += wp[m] * yb[m * 128];
    const float a = 1.f / (1.f + __expf(-s));
    ((tid < 64) ? g_ah : g_aw)[bc * 64 + l] = a;
}

// ---------------------------------------------------------------------------
// Kernel 3: pure stream: out = x * ah[h] * aw[w]. Reverse order for L2 reuse.
// Front-batched x loads + streaming stores.
// ---------------------------------------------------------------------------
__global__ __launch_bounds__(256) void k_apply(
    const float* __restrict__ x, float* __restrict__ out)
{
    const int bc  = (NB * NC - 1) - blockIdx.x;
    const int tid = threadIdx.x;

    const float4* x4  = (const float4*)(x   + (size_t)bc * (NH * NW));
    float4*       o4  = (float4*)      (out + (size_t)bc * (NH * NW));
    const float*  ahp = g_ah + bc * 64;
    const float4* awp = (const float4*)(g_aw + bc * 64);

    float4 xv[4];
#pragma unroll
    for (int i = 0; i < 4; i++) xv[i] = __ldg(&x4[tid + i * 256]);

#pragma unroll
    for (int i = 0; i < 4; i++) {
        const int f  = tid + i * 256;    // 0..1023
        const int h  = f >> 4;           // 0..63
        const int w4 = f & 15;           // 0..15
        const float  a1 = __ldg(&ahp[h]);
        const float4 a2 = __ldg(&awp[w4]);
        float4 o;
        o.x = xv[i].x * a1 * a2.x;
        o.y = xv[i].y * a1 * a2.y;
        o.z = xv[i].z * a1 * a2.z;
        o.w = xv[i].w * a1 * a2.w;
        __stcs(&o4[f], o);               // streaming store: evict-first in L2
    }
}

// ---------------------------------------------------------------------------
extern "C" void kernel_launch(void* const* d_in, const int* in_sizes, int n_in,
                              void* d_out, int out_size)
{
    const float* x       = (const float*)d_in[0];
    const float* sph_w3  = (const float*)d_in[1];
    const float* sph_w7  = (const float*)d_in[2];
    const float* sph_g   = (const float*)d_in[3];
    const float* sph_b   = (const float*)d_in[4];
    const float* sph_m   = (const float*)d_in[5];
    const float* sph_v   = (const float*)d_in[6];
    const float* spw_w3  = (const float*)d_in[7];
    const float* spw_w7  = (const float*)d_in[8];
    const float* spw_g   = (const float*)d_in[9];
    const float* spw_b   = (const float*)d_in[10];
    const float* spw_m   = (const float*)d_in[11];
    const float* spw_v   = (const float*)d_in[12];
    const float* conv1_w = (const float*)d_in[13];
    const float* bn1_g   = (const float*)d_in[14];
    const float* bn1_b   = (const float*)d_in[15];
    const float* bn1_m   = (const float*)d_in[16];
    const float* bn1_v   = (const float*)d_in[17];
    const float* convh_w = (const float*)d_in[18];
    const float* convw_w = (const float*)d_in[19];
    float* out = (float*)d_out;

    k_reduce_strip<<<NB * NC, 128>>>(x,
        sph_w3, sph_w7, sph_g, sph_b, sph_m, sph_v,
        spw_w3, spw_w7, spw_g, spw_b, spw_m, spw_v);

    k_y<<<NB, 256>>>(conv1_w, bn1_g, bn1_b, bn1_m, bn1_v);

    k_att<<<NB * NC, 128>>>(convh_w, convw_w);

    k_apply<<<NB * NC, 256>>>(x, out);
}

// round 12
// speedup vs baseline: 1.2095x; 1.1213x over previous
#include <cuda_runtime.h>
#include <math.h>
#include <stdint.h>

#define NB 32
#define NC 256
#define NH 64
#define NW 64
#define MIP 8
#define EPS 1e-5f

// Intermediates (no allocation allowed -> device globals)
__device__ __align__(16) float g_s [NB * NC * 128];   // strip-pooled+BN : 4 MB
__device__ __align__(16) float g_y [NB * MIP * 128];  // conv1+BN+hswish : 128 KB
__device__ __align__(16) float g_ah[NB * NC * NH];    // 2 MB
__device__ __align__(16) float g_aw[NB * NC * NW];    // 2 MB

// ---------------------------------------------------------------------------
// Kernel 1: per (b,c) slice -> row/col means -> conv3+conv7 -> BN.
// TMA bulk copy (16 KB slice -> smem) replaces per-thread LDG: bypasses the
// L1tex wavefront queue, in flight from cycle 0, zero register pressure.
// Same block->bc mapping/order as R7 (preserves L2 tail for k_apply).
// ---------------------------------------------------------------------------
__global__ __launch_bounds__(128) void k_reduce_strip(
    const float* __restrict__ x,
    const float* __restrict__ sph_w3, const float* __restrict__ sph_w7,
    const float* __restrict__ sph_g,  const float* __restrict__ sph_b,
    const float* __restrict__ sph_m,  const float* __restrict__ sph_v,
    const float* __restrict__ spw_w3, const float* __restrict__ spw_w7,
    const float* __restrict__ spw_g,  const float* __restrict__ spw_b,
    const float* __restrict__ spw_m,  const float* __restrict__ spw_v)
{
    __shared__ __align__(128) float tile[NH * NW];     // 16 KB
    __shared__ unsigned long long mbar;
    __shared__ __align__(16) float4 csum[128];         // column partials (2 KB)
    __shared__ float  mrow[NH];
    __shared__ float  mcol[NW];

    const int bc  = blockIdx.x;       // b*256 + c
    const int c   = bc & (NC - 1);
    const int tid = threadIdx.x;      // 0..127
    const int grp = tid >> 4;         // 0..7 (row-group)
    const int w4  = tid & 15;         // float4 chunk along W

    const uint32_t mbar_a = (uint32_t)__cvta_generic_to_shared(&mbar);
    const uint32_t tile_a = (uint32_t)__cvta_generic_to_shared(tile);

    if (tid == 0) {
        asm volatile("mbarrier.init.shared.b64 [%0], 1;" :: "r"(mbar_a) : "memory");
    }
    __syncthreads();
    if (tid == 0) {
        asm volatile("mbarrier.arrive.expect_tx.shared.b64 _, [%0], %1;"
                     :: "r"(mbar_a), "r"(16384u) : "memory");
        asm volatile(
            "cp.async.bulk.shared::cta.global.mbarrier::complete_tx::bytes "
            "[%0], [%1], %2, [%3];"
            :: "r"(tile_a), "l"(x + (size_t)bc * (NH * NW)), "r"(16384u), "r"(mbar_a)
            : "memory");
    }
    // Wait for TMA completion (phase parity 0, acquire)
    {
        uint32_t done = 0;
        while (!done) {
            asm volatile(
                "{\n\t.reg .pred p;\n\t"
                "mbarrier.try_wait.parity.acquire.cta.shared::cta.b64 p, [%1], 0;\n\t"
                "selp.b32 %0, 1, 0, p;\n\t}"
                : "=r"(done) : "r"(mbar_a) : "memory");
        }
    }

    // 8 float4 reads per thread from smem: f = tid + 128*i -> row h = grp + 8*i
    const float4* t4 = (const float4*)tile;
    float4 v0 = t4[tid];
    float4 v1 = t4[tid + 128];
    float4 v2 = t4[tid + 256];
    float4 v3 = t4[tid + 384];
    float4 v4 = t4[tid + 512];
    float4 v5 = t4[tid + 640];
    float4 v6 = t4[tid + 768];
    float4 v7 = t4[tid + 896];

    // Column partials over this thread's 8 rows
    float4 cs;
    cs.x = (v0.x + v1.x) + (v2.x + v3.x) + ((v4.x + v5.x) + (v6.x + v7.x));
    cs.y = (v0.y + v1.y) + (v2.y + v3.y) + ((v4.y + v5.y) + (v6.y + v7.y));
    cs.z = (v0.z + v1.z) + (v2.z + v3.z) + ((v4.z + v5.z) + (v6.z + v7.z));
    cs.w = (v0.w + v1.w) + (v2.w + v3.w) + ((v4.w + v5.w) + (v6.w + v7.w));
    csum[tid] = cs;

    // Row chunk sums; reduce across the 16 lanes sharing grp
    float r0 = v0.x + v0.y + v0.z + v0.w;
    float r1 = v1.x + v1.y + v1.z + v1.w;
    float r2 = v2.x + v2.y + v2.z + v2.w;
    float r3 = v3.x + v3.y + v3.z + v3.w;
    float r4 = v4.x + v4.y + v4.z + v4.w;
    float r5 = v5.x + v5.y + v5.z + v5.w;
    float r6 = v6.x + v6.y + v6.z + v6.w;
    float r7 = v7.x + v7.y + v7.z + v7.w;
#pragma unroll
    for (int m = 8; m >= 1; m >>= 1) {
        r0 += __shfl_xor_sync(0xffffffffu, r0, m);
        r1 += __shfl_xor_sync(0xffffffffu, r1, m);
        r2 += __shfl_xor_sync(0xffffffffu, r2, m);
        r3 += __shfl_xor_sync(0xffffffffu, r3, m);
        r4 += __shfl_xor_sync(0xffffffffu, r4, m);
        r5 += __shfl_xor_sync(0xffffffffu, r5, m);
        r6 += __shfl_xor_sync(0xffffffffu, r6, m);
        r7 += __shfl_xor_sync(0xffffffffu, r7, m);
    }
    if (w4 == 0) {
        mrow[grp]      = r0 * (1.f / 64.f);
        mrow[grp + 8]  = r1 * (1.f / 64.f);
        mrow[grp + 16] = r2 * (1.f / 64.f);
        mrow[grp + 24] = r3 * (1.f / 64.f);
        mrow[grp + 32] = r4 * (1.f / 64.f);
        mrow[grp + 40] = r5 * (1.f / 64.f);
        mrow[grp + 48] = r6 * (1.f / 64.f);
        mrow[grp + 56] = r7 * (1.f / 64.f);
    }
    __syncthreads();

    // Column sums: thread w (<64) reduces column w over 8 row-groups.
    if (tid < 64) {
        const float* cf = (const float*)csum;
        float s = 0.f;
#pragma unroll
        for (int g = 0; g < 8; g++) s += cf[g * 64 + tid];
        mcol[tid] = s * (1.f / 64.f);
    }
    __syncthreads();

    // Strip pool: (x + conv3(x) + conv7(x))/3, then BN. All 128 threads.
    {
        const int l = tid & 63;
        const float* src; const float* w3; const float* w7;
        float g, bb, mm, vv; int off;
        if (tid < 64) {
            src = mrow; w3 = sph_w3 + c * 3; w7 = sph_w7 + c * 7;
            g = sph_g[c]; bb = sph_b[c]; mm = sph_m[c]; vv = sph_v[c]; off = 0;
        } else {
            src = mcol; w3 = spw_w3 + c * 3; w7 = spw_w7 + c * 7;
            g = spw_g[c]; bb = spw_b[c]; mm = spw_m[c]; vv = spw_v[c]; off = 64;
        }

        float acc = src[l];
#pragma unroll
        for (int j = 0; j < 3; j++) {
            int idx = l + j - 1;
            if (idx >= 0 && idx < 64) acc += src[idx] * w3[j];
        }
#pragma unroll
        for (int j = 0; j < 7; j++) {
            int idx = l + j - 3;
            if (idx >= 0 && idx < 64) acc += src[idx] * w7[j];
        }
        acc *= (1.f / 3.f);
        const float scale = g * rsqrtf(vv + EPS);
        g_s[(size_t)bc * 128 + off + l] = (acc - mm) * scale + bb;
    }
}

// ---------------------------------------------------------------------------
// Kernel 2: conv1 (C->MIP) + BN1 + hswish -> g_y.
// Grid = NB*4 (b, l-group of 32). Block 256 = 8 channel-groups x 32 l.
// ---------------------------------------------------------------------------
__global__ __launch_bounds__(256) void k_y(
    const float* __restrict__ conv1_w,
    const float* __restrict__ bn1_g, const float* __restrict__ bn1_b,
    const float* __restrict__ bn1_m, const float* __restrict__ bn1_v)
{
    __shared__ float w1s[MIP * NC];        // 8 KB
    __shared__ float part[8][MIP * 32];    // 8 KB

    const int b   = blockIdx.x >> 2;
    const int lg  = blockIdx.x & 3;
    const int tid = threadIdx.x;
    const int cg  = tid >> 5;              // channel group 0..7
    const int l   = tid & 31;              // l within group

#pragma unroll
    for (int i = 0; i < MIP; i++) w1s[tid + i * NC] = conv1_w[tid + i * NC];
    __syncthreads();

    float acc[MIP];
#pragma unroll
    for (int m = 0; m < MIP; m++) acc[m] = 0.f;

    const float* sp = g_s + (size_t)b * NC * 128 + (size_t)(cg * 32) * 128 + lg * 32 + l;
#pragma unroll 8
    for (int cc = 0; cc < 32; cc++) {
        const float v = sp[cc * 128];      // coalesced over l
#pragma unroll
        for (int m = 0; m < MIP; m++) acc[m] += w1s[m * NC + cg * 32 + cc] * v;
    }
#pragma unroll
    for (int m = 0; m < MIP; m++) part[cg][m * 32 + l] = acc[m];
    __syncthreads();

    {
        float s = 0.f;
#pragma unroll
        for (int g = 0; g < 8; g++) s += part[g][tid];
        const int m = tid >> 5;
        const float scale = bn1_g[m] * rsqrtf(bn1_v[m] + EPS);
        const float val   = (s - bn1_m[m]) * scale + bn1_b[m];
        g_y[(size_t)b * (MIP * 128) + m * 128 + lg * 32 + (tid & 31)] =
            val * fminf(fmaxf(val + 3.f, 0.f), 6.f) * (1.f / 6.f);
    }
}

// ---------------------------------------------------------------------------
// Kernel 2b: attention weights. One block per (b,c), 128 threads.
// ---------------------------------------------------------------------------
__global__ __launch_bounds__(128) void k_att(
    const float* __restrict__ convh_w, const float* __restrict__ convw_w)
{
    const int bc  = blockIdx.x;
    const int b   = bc >> 8;
    const int c   = bc & 255;
    const int tid = threadIdx.x;
    const int l   = tid & 63;
    const int off = (tid < 64) ? 0 : 64;

    const float* yb = g_y + (size_t)b * (MIP * 128) + off + l;
    const float* wp = ((tid < 64) ? convh_w : convw_w) + c * MIP;

    float s = 0.f;
#pragma unroll
    for (int m = 0; m < MIP; m++) s += wp[m] * yb[m * 128];
    const float a = 1.f / (1.f + __expf(-s));
    ((tid < 64) ? g_ah : g_aw)[bc * 64 + l] = a;
}

// ---------------------------------------------------------------------------
// Kernel 3: pure stream: out = x * ah[h] * aw[w]. Reverse order for L2 reuse.
// Front-batched x loads + streaming stores.  (unchanged — 70% DRAM)
// ---------------------------------------------------------------------------
__global__ __launch_bounds__(256) void k_apply(
    const float* __restrict__ x, float* __restrict__ out)
{
    const int bc  = (NB * NC - 1) - blockIdx.x;
    const int tid = threadIdx.x;

    const float4* x4  = (const float4*)(x   + (size_t)bc * (NH * NW));
    float4*       o4  = (float4*)      (out + (size_t)bc * (NH * NW));
    const float*  ahp = g_ah + bc * 64;
    const float4* awp = (const float4*)(g_aw + bc * 64);

    float4 xv[4];
#pragma unroll
    for (int i = 0; i < 4; i++) xv[i] = __ldg(&x4[tid + i * 256]);

#pragma unroll
    for (int i = 0; i < 4; i++) {
        const int f  = tid + i * 256;    // 0..1023
        const int h  = f >> 4;           // 0..63
        const int w4 = f & 15;           // 0..15
        const float  a1 = __ldg(&ahp[h]);
        const float4 a2 = __ldg(&awp[w4]);
        float4 o;
        o.x = xv[i].x * a1 * a2.x;
        o.y = xv[i].y * a1 * a2.y;
        o.z = xv[i].z * a1 * a2.z;
        o.w = xv[i].w * a1 * a2.w;
        __stcs(&o4[f], o);               // streaming store: evict-first in L2
    }
}

// ---------------------------------------------------------------------------
extern "C" void kernel_launch(void* const* d_in, const int* in_sizes, int n_in,
                              void* d_out, int out_size)
{
    const float* x       = (const float*)d_in[0];
    const float* sph_w3  = (const float*)d_in[1];
    const float* sph_w7  = (const float*)d_in[2];
    const float* sph_g   = (const float*)d_in[3];
    const float* sph_b   = (const float*)d_in[4];
    const float* sph_m   = (const float*)d_in[5];
    const float* sph_v   = (const float*)d_in[6];
    const float* spw_w3  = (const float*)d_in[7];
    const float* spw_w7  = (const float*)d_in[8];
    const float* spw_g   = (const float*)d_in[9];
    const float* spw_b   = (const float*)d_in[10];
    const float* spw_m   = (const float*)d_in[11];
    const float* spw_v   = (const float*)d_in[12];
    const float* conv1_w = (const float*)d_in[13];
    const float* bn1_g   = (const float*)d_in[14];
    const float* bn1_b   = (const float*)d_in[15];
    const float* bn1_m   = (const float*)d_in[16];
    const float* bn1_v   = (const float*)d_in[17];
    const float* convh_w = (const float*)d_in[18];
    const float* convw_w = (const float*)d_in[19];
    float* out = (float*)d_out;

    k_reduce_strip<<<NB * NC, 128>>>(x,
        sph_w3, sph_w7, sph_g, sph_b, sph_m, sph_v,
        spw_w3, spw_w7, spw_g, spw_b, spw_m, spw_v);

    k_y<<<NB * 4, 256>>>(conv1_w, bn1_g, bn1_b, bn1_m, bn1_v);

    k_att<<<NB * NC, 128>>>(convh_w, convw_w);

    k_apply<<<NB * NC, 256>>>(x, out);
}

// round 13
// speedup vs baseline: 1.2809x; 1.0590x over previous
#include <cuda_runtime.h>
#include <math.h>
#include <stdint.h>

#define NB 32
#define NC 256
#define NH 64
#define NW 64
#define MIP 8
#define EPS 1e-5f

// Intermediates (no allocation allowed -> device globals)
__device__ __align__(16) float g_s [NB * NC * 128];   // strip-pooled+BN : 4 MB
__device__ __align__(16) float g_y [NB * MIP * 128];  // conv1+BN+hswish : 128 KB

// ---------------------------------------------------------------------------
// Kernel 1: per (b,c) slice -> row/col means -> conv3+conv7 -> BN.
// TMA bulk copy (16 KB slice -> smem). (R12 version — proven)
// ---------------------------------------------------------------------------
__global__ __launch_bounds__(128) void k_reduce_strip(
    const float* __restrict__ x,
    const float* __restrict__ sph_w3, const float* __restrict__ sph_w7,
    const float* __restrict__ sph_g,  const float* __restrict__ sph_b,
    const float* __restrict__ sph_m,  const float* __restrict__ sph_v,
    const float* __restrict__ spw_w3, const float* __restrict__ spw_w7,
    const float* __restrict__ spw_g,  const float* __restrict__ spw_b,
    const float* __restrict__ spw_m,  const float* __restrict__ spw_v)
{
    __shared__ __align__(128) float tile[NH * NW];     // 16 KB
    __shared__ unsigned long long mbar;
    __shared__ __align__(16) float4 csum[128];         // column partials (2 KB)
    __shared__ float  mrow[NH];
    __shared__ float  mcol[NW];

    const int bc  = blockIdx.x;       // b*256 + c
    const int c   = bc & (NC - 1);
    const int tid = threadIdx.x;      // 0..127
    const int grp = tid >> 4;         // 0..7 (row-group)
    const int w4  = tid & 15;         // float4 chunk along W

    const uint32_t mbar_a = (uint32_t)__cvta_generic_to_shared(&mbar);
    const uint32_t tile_a = (uint32_t)__cvta_generic_to_shared(tile);

    if (tid == 0) {
        asm volatile("mbarrier.init.shared.b64 [%0], 1;" :: "r"(mbar_a) : "memory");
    }
    __syncthreads();
    if (tid == 0) {
        asm volatile("mbarrier.arrive.expect_tx.shared.b64 _, [%0], %1;"
                     :: "r"(mbar_a), "r"(16384u) : "memory");
        asm volatile(
            "cp.async.bulk.shared::cta.global.mbarrier::complete_tx::bytes "
            "[%0], [%1], %2, [%3];"
            :: "r"(tile_a), "l"(x + (size_t)bc * (NH * NW)), "r"(16384u), "r"(mbar_a)
            : "memory");
    }
    {
        uint32_t done = 0;
        while (!done) {
            asm volatile(
                "{\n\t.reg .pred p;\n\t"
                "mbarrier.try_wait.parity.acquire.cta.shared::cta.b64 p, [%1], 0;\n\t"
                "selp.b32 %0, 1, 0, p;\n\t}"
                : "=r"(done) : "r"(mbar_a) : "memory");
        }
    }

    const float4* t4 = (const float4*)tile;
    float4 v0 = t4[tid];
    float4 v1 = t4[tid + 128];
    float4 v2 = t4[tid + 256];
    float4 v3 = t4[tid + 384];
    float4 v4 = t4[tid + 512];
    float4 v5 = t4[tid + 640];
    float4 v6 = t4[tid + 768];
    float4 v7 = t4[tid + 896];

    float4 cs;
    cs.x = (v0.x + v1.x) + (v2.x + v3.x) + ((v4.x + v5.x) + (v6.x + v7.x));
    cs.y = (v0.y + v1.y) + (v2.y + v3.y) + ((v4.y + v5.y) + (v6.y + v7.y));
    cs.z = (v0.z + v1.z) + (v2.z + v3.z) + ((v4.z + v5.z) + (v6.z + v7.z));
    cs.w = (v0.w + v1.w) + (v2.w + v3.w) + ((v4.w + v5.w) + (v6.w + v7.w));
    csum[tid] = cs;

    float r0 = v0.x + v0.y + v0.z + v0.w;
    float r1 = v1.x + v1.y + v1.z + v1.w;
    float r2 = v2.x + v2.y + v2.z + v2.w;
    float r3 = v3.x + v3.y + v3.z + v3.w;
    float r4 = v4.x + v4.y + v4.z + v4.w;
    float r5 = v5.x + v5.y + v5.z + v5.w;
    float r6 = v6.x + v6.y + v6.z + v6.w;
    float r7 = v7.x + v7.y + v7.z + v7.w;
#pragma unroll
    for (int m = 8; m >= 1; m >>= 1) {
        r0 += __shfl_xor_sync(0xffffffffu, r0, m);
        r1 += __shfl_xor_sync(0xffffffffu, r1, m);
        r2 += __shfl_xor_sync(0xffffffffu, r2, m);
        r3 += __shfl_xor_sync(0xffffffffu, r3, m);
        r4 += __shfl_xor_sync(0xffffffffu, r4, m);
        r5 += __shfl_xor_sync(0xffffffffu, r5, m);
        r6 += __shfl_xor_sync(0xffffffffu, r6, m);
        r7 += __shfl_xor_sync(0xffffffffu, r7, m);
    }
    if (w4 == 0) {
        mrow[grp]      = r0 * (1.f / 64.f);
        mrow[grp + 8]  = r1 * (1.f / 64.f);
        mrow[grp + 16] = r2 * (1.f / 64.f);
        mrow[grp + 24] = r3 * (1.f / 64.f);
        mrow[grp + 32] = r4 * (1.f / 64.f);
        mrow[grp + 40] = r5 * (1.f / 64.f);
        mrow[grp + 48] = r6 * (1.f / 64.f);
        mrow[grp + 56] = r7 * (1.f / 64.f);
    }
    __syncthreads();

    if (tid < 64) {
        const float* cf = (const float*)csum;
        float s = 0.f;
#pragma unroll
        for (int g = 0; g < 8; g++) s += cf[g * 64 + tid];
        mcol[tid] = s * (1.f / 64.f);
    }
    __syncthreads();

    {
        const int l = tid & 63;
        const float* src; const float* w3; const float* w7;
        float g, bb, mm, vv; int off;
        if (tid < 64) {
            src = mrow; w3 = sph_w3 + c * 3; w7 = sph_w7 + c * 7;
            g = sph_g[c]; bb = sph_b[c]; mm = sph_m[c]; vv = sph_v[c]; off = 0;
        } else {
            src = mcol; w3 = spw_w3 + c * 3; w7 = spw_w7 + c * 7;
            g = spw_g[c]; bb = spw_b[c]; mm = spw_m[c]; vv = spw_v[c]; off = 64;
        }

        float acc = src[l];
#pragma unroll
        for (int j = 0; j < 3; j++) {
            int idx = l + j - 1;
            if (idx >= 0 && idx < 64) acc += src[idx] * w3[j];
        }
#pragma unroll
        for (int j = 0; j < 7; j++) {
            int idx = l + j - 3;
            if (idx >= 0 && idx < 64) acc += src[idx] * w7[j];
        }
        acc *= (1.f / 3.f);
        const float scale = g * rsqrtf(vv + EPS);
        g_s[(size_t)bc * 128 + off + l] = (acc - mm) * scale + bb;
    }
}

// ---------------------------------------------------------------------------
// Kernel 2: conv1 (C->MIP) + BN1 + hswish -> g_y.  (R12 version)
// ---------------------------------------------------------------------------
__global__ __launch_bounds__(256) void k_y(
    const float* __restrict__ conv1_w,
    const float* __restrict__ bn1_g, const float* __restrict__ bn1_b,
    const float* __restrict__ bn1_m, const float* __restrict__ bn1_v)
{
    __shared__ float w1s[MIP * NC];        // 8 KB
    __shared__ float part[8][MIP * 32];    // 8 KB

    const int b   = blockIdx.x >> 2;
    const int lg  = blockIdx.x & 3;
    const int tid = threadIdx.x;
    const int cg  = tid >> 5;              // channel group 0..7
    const int l   = tid & 31;              // l within group

#pragma unroll
    for (int i = 0; i < MIP; i++) w1s[tid + i * NC] = conv1_w[tid + i * NC];
    __syncthreads();

    float acc[MIP];
#pragma unroll
    for (int m = 0; m < MIP; m++) acc[m] = 0.f;

    const float* sp = g_s + (size_t)b * NC * 128 + (size_t)(cg * 32) * 128 + lg * 32 + l;
#pragma unroll 8
    for (int cc = 0; cc < 32; cc++) {
        const float v = sp[cc * 128];
#pragma unroll
        for (int m = 0; m < MIP; m++) acc[m] += w1s[m * NC + cg * 32 + cc] * v;
    }
#pragma unroll
    for (int m = 0; m < MIP; m++) part[cg][m * 32 + l] = acc[m];
    __syncthreads();

    {
        float s = 0.f;
#pragma unroll
        for (int g = 0; g < 8; g++) s += part[g][tid];
        const int m = tid >> 5;
        const float scale = bn1_g[m] * rsqrtf(bn1_v[m] + EPS);
        const float val   = (s - bn1_m[m]) * scale + bn1_b[m];
        g_y[(size_t)b * (MIP * 128) + m * 128 + lg * 32 + (tid & 31)] =
            val * fminf(fmaxf(val + 3.f, 0.f), 6.f) * (1.f / 6.f);
    }
}

// ---------------------------------------------------------------------------
// Kernel 3 (fused): attention + stream. Per (b,c) block:
//   - front-batch the 4 x float4 loads (DRAM latency starts immediately)
//   - threads 0..127 compute ah/aw from g_y (L2-hot) + convh/convw + sigmoid
//   - one sync, then multiply + streaming store.
// Reverse bc order preserves the L2-tail trick.
// ---------------------------------------------------------------------------
__global__ __launch_bounds__(256) void k_apply(
    const float* __restrict__ x,
    const float* __restrict__ convh_w, const float* __restrict__ convw_w,
    float* __restrict__ out)
{
    __shared__ __align__(16) float ah[64];
    __shared__ __align__(16) float aw[64];

    const int bc  = (NB * NC - 1) - blockIdx.x;
    const int b   = bc >> 8;
    const int c   = bc & 255;
    const int tid = threadIdx.x;

    const float4* x4 = (const float4*)(x   + (size_t)bc * (NH * NW));
    float4*       o4 = (float4*)      (out + (size_t)bc * (NH * NW));

    // Front-batch x loads: in flight before/through the attention prologue.
    float4 xv[4];
#pragma unroll
    for (int i = 0; i < 4; i++) xv[i] = __ldg(&x4[tid + i * 256]);

    // Attention prologue (threads 0..127): 8 L2-hot y loads + sigmoid.
    if (tid < 128) {
        const int l   = tid & 63;
        const int off = (tid < 64) ? 0 : 64;
        const float* yb = g_y + (size_t)b * (MIP * 128) + off + l;
        const float* wp = ((tid < 64) ? convh_w : convw_w) + c * MIP;
        float s = 0.f;
#pragma unroll
        for (int m = 0; m < MIP; m++) s += wp[m] * __ldg(&yb[m * 128]);
        const float a = 1.f / (1.f + __expf(-s));
        ((tid < 64) ? ah : aw)[l] = a;
    }
    __syncthreads();

#pragma unroll
    for (int i = 0; i < 4; i++) {
        const int f  = tid + i * 256;    // 0..1023
        const int h  = f >> 4;           // 0..63
        const int w4 = f & 15;           // 0..15
        const float  a1 = ah[h];
        const float4 a2 = ((const float4*)aw)[w4];
        float4 o;
        o.x = xv[i].x * a1 * a2.x;
        o.y = xv[i].y * a1 * a2.y;
        o.z = xv[i].z * a1 * a2.z;
        o.w = xv[i].w * a1 * a2.w;
        __stcs(&o4[f], o);               // streaming store: evict-first in L2
    }
}

// ---------------------------------------------------------------------------
extern "C" void kernel_launch(void* const* d_in, const int* in_sizes, int n_in,
                              void* d_out, int out_size)
{
    const float* x       = (const float*)d_in[0];
    const float* sph_w3  = (const float*)d_in[1];
    const float* sph_w7  = (const float*)d_in[2];
    const float* sph_g   = (const float*)d_in[3];
    const float* sph_b   = (const float*)d_in[4];
    const float* sph_m   = (const float*)d_in[5];
    const float* sph_v   = (const float*)d_in[6];
    const float* spw_w3  = (const float*)d_in[7];
    const float* spw_w7  = (const float*)d_in[8];
    const float* spw_g   = (const float*)d_in[9];
    const float* spw_b   = (const float*)d_in[10];
    const float* spw_m   = (const float*)d_in[11];
    const float* spw_v   = (const float*)d_in[12];
    const float* conv1_w = (const float*)d_in[13];
    const float* bn1_g   = (const float*)d_in[14];
    const float* bn1_b   = (const float*)d_in[15];
    const float* bn1_m   = (const float*)d_in[16];
    const float* bn1_v   = (const float*)d_in[17];
    const float* convh_w = (const float*)d_in[18];
    const float* convw_w = (const float*)d_in[19];
    float* out = (float*)d_out;

    k_reduce_strip<<<NB * NC, 128>>>(x,
        sph_w3, sph_w7, sph_g, sph_b, sph_m, sph_v,
        spw_w3, spw_w7, spw_g, spw_b, spw_m, spw_v);

    k_y<<<NB * 4, 256>>>(conv1_w, bn1_g, bn1_b, bn1_m, bn1_v);

    k_apply<<<NB * NC, 256>>>(x, convh_w, convw_w, out);
}

// round 15
// speedup vs baseline: 1.3437x; 1.0490x over previous
#include <cuda_runtime.h>
#include <math.h>
#include <stdint.h>

#define NB 32
#define NC 256
#define NH 64
#define NW 64
#define MIP 8
#define EPS 1e-5f

// Intermediates (no allocation allowed -> device globals)
__device__ __align__(16) float g_s [NB * NC * 128];   // strip-pooled+BN : 4 MB
__device__ __align__(16) float g_y [NB * MIP * 128];  // conv1+BN+hswish : 128 KB

// ---------------------------------------------------------------------------
// Kernel 1: per (b,c) slice -> row/col means -> conv3+conv7 -> BN.
// TMA bulk copy (16 KB slice -> smem). (R12 version — proven)
// ---------------------------------------------------------------------------
__global__ __launch_bounds__(128) void k_reduce_strip(
    const float* __restrict__ x,
    const float* __restrict__ sph_w3, const float* __restrict__ sph_w7,
    const float* __restrict__ sph_g,  const float* __restrict__ sph_b,
    const float* __restrict__ sph_m,  const float* __restrict__ sph_v,
    const float* __restrict__ spw_w3, const float* __restrict__ spw_w7,
    const float* __restrict__ spw_g,  const float* __restrict__ spw_b,
    const float* __restrict__ spw_m,  const float* __restrict__ spw_v)
{
    __shared__ __align__(128) float tile[NH * NW];     // 16 KB
    __shared__ unsigned long long mbar;
    __shared__ __align__(16) float4 csum[128];         // column partials (2 KB)
    __shared__ float  mrow[NH];
    __shared__ float  mcol[NW];

    const int bc  = blockIdx.x;       // b*256 + c
    const int c   = bc & (NC - 1);
    const int tid = threadIdx.x;      // 0..127
    const int grp = tid >> 4;         // 0..7 (row-group)
    const int w4  = tid & 15;         // float4 chunk along W

    const uint32_t mbar_a = (uint32_t)__cvta_generic_to_shared(&mbar);
    const uint32_t tile_a = (uint32_t)__cvta_generic_to_shared(tile);

    if (tid == 0) {
        asm volatile("mbarrier.init.shared.b64 [%0], 1;" :: "r"(mbar_a) : "memory");
    }
    __syncthreads();
    if (tid == 0) {
        asm volatile("mbarrier.arrive.expect_tx.shared.b64 _, [%0], %1;"
                     :: "r"(mbar_a), "r"(16384u) : "memory");
        asm volatile(
            "cp.async.bulk.shared::cta.global.mbarrier::complete_tx::bytes "
            "[%0], [%1], %2, [%3];"
            :: "r"(tile_a), "l"(x + (size_t)bc * (NH * NW)), "r"(16384u), "r"(mbar_a)
            : "memory");
    }
    {
        uint32_t done = 0;
        while (!done) {
            asm volatile(
                "{\n\t.reg .pred p;\n\t"
                "mbarrier.try_wait.parity.acquire.cta.shared::cta.b64 p, [%1], 0;\n\t"
                "selp.b32 %0, 1, 0, p;\n\t}"
                : "=r"(done) : "r"(mbar_a) : "memory");
        }
    }

    const float4* t4 = (const float4*)tile;
    float4 v0 = t4[tid];
    float4 v1 = t4[tid + 128];
    float4 v2 = t4[tid + 256];
    float4 v3 = t4[tid + 384];
    float4 v4 = t4[tid + 512];
    float4 v5 = t4[tid + 640];
    float4 v6 = t4[tid + 768];
    float4 v7 = t4[tid + 896];

    float4 cs;
    cs.x = (v0.x + v1.x) + (v2.x + v3.x) + ((v4.x + v5.x) + (v6.x + v7.x));
    cs.y = (v0.y + v1.y) + (v2.y + v3.y) + ((v4.y + v5.y) + (v6.y + v7.y));
    cs.z = (v0.z + v1.z) + (v2.z + v3.z) + ((v4.z + v5.z) + (v6.z + v7.z));
    cs.w = (v0.w + v1.w) + (v2.w + v3.w) + ((v4.w + v5.w) + (v6.w + v7.w));
    csum[tid] = cs;

    float r0 = v0.x + v0.y + v0.z + v0.w;
    float r1 = v1.x + v1.y + v1.z + v1.w;
    float r2 = v2.x + v2.y + v2.z + v2.w;
    float r3 = v3.x + v3.y + v3.z + v3.w;
    float r4 = v4.x + v4.y + v4.z + v4.w;
    float r5 = v5.x + v5.y + v5.z + v5.w;
    float r6 = v6.x + v6.y + v6.z + v6.w;
    float r7 = v7.x + v7.y + v7.z + v7.w;
#pragma unroll
    for (int m = 8; m >= 1; m >>= 1) {
        r0 += __shfl_xor_sync(0xffffffffu, r0, m);
        r1 += __shfl_xor_sync(0xffffffffu, r1, m);
        r2 += __shfl_xor_sync(0xffffffffu, r2, m);
        r3 += __shfl_xor_sync(0xffffffffu, r3, m);
        r4 += __shfl_xor_sync(0xffffffffu, r4, m);
        r5 += __shfl_xor_sync(0xffffffffu, r5, m);
        r6 += __shfl_xor_sync(0xffffffffu, r6, m);
        r7 += __shfl_xor_sync(0xffffffffu, r7, m);
    }
    if (w4 == 0) {
        mrow[grp]      = r0 * (1.f / 64.f);
        mrow[grp + 8]  = r1 * (1.f / 64.f);
        mrow[grp + 16] = r2 * (1.f / 64.f);
        mrow[grp + 24] = r3 * (1.f / 64.f);
        mrow[grp + 32] = r4 * (1.f / 64.f);
        mrow[grp + 40] = r5 * (1.f / 64.f);
        mrow[grp + 48] = r6 * (1.f / 64.f);
        mrow[grp + 56] = r7 * (1.f / 64.f);
    }
    __syncthreads();

    if (tid < 64) {
        const float* cf = (const float*)csum;
        float s = 0.f;
#pragma unroll
        for (int g = 0; g < 8; g++) s += cf[g * 64 + tid];
        mcol[tid] = s * (1.f / 64.f);
    }
    __syncthreads();

    {
        const int l = tid & 63;
        const float* src; const float* w3; const float* w7;
        float g, bb, mm, vv; int off;
        if (tid < 64) {
            src = mrow; w3 = sph_w3 + c * 3; w7 = sph_w7 + c * 7;
            g = sph_g[c]; bb = sph_b[c]; mm = sph_m[c]; vv = sph_v[c]; off = 0;
        } else {
            src = mcol; w3 = spw_w3 + c * 3; w7 = spw_w7 + c * 7;
            g = spw_g[c]; bb = spw_b[c]; mm = spw_m[c]; vv = spw_v[c]; off = 64;
        }

        float acc = src[l];
#pragma unroll
        for (int j = 0; j < 3; j++) {
            int idx = l + j - 1;
            if (idx >= 0 && idx < 64) acc += src[idx] * w3[j];
        }
#pragma unroll
        for (int j = 0; j < 7; j++) {
            int idx = l + j - 3;
            if (idx >= 0 && idx < 64) acc += src[idx] * w7[j];
        }
        acc *= (1.f / 3.f);
        const float scale = g * rsqrtf(vv + EPS);
        g_s[(size_t)bc * 128 + off + l] = (acc - mm) * scale + bb;
    }
}

// ---------------------------------------------------------------------------
// Kernel 2: conv1 (C->MIP) + BN1 + hswish -> g_y.  (R12 version)
// ---------------------------------------------------------------------------
__global__ __launch_bounds__(256) void k_y(
    const float* __restrict__ conv1_w,
    const float* __restrict__ bn1_g, const float* __restrict__ bn1_b,
    const float* __restrict__ bn1_m, const float* __restrict__ bn1_v)
{
    __shared__ float w1s[MIP * NC];        // 8 KB
    __shared__ float part[8][MIP * 32];    // 8 KB

    const int b   = blockIdx.x >> 2;
    const int lg  = blockIdx.x & 3;
    const int tid = threadIdx.x;
    const int cg  = tid >> 5;              // channel group 0..7
    const int l   = tid & 31;              // l within group

#pragma unroll
    for (int i = 0; i < MIP; i++) w1s[tid + i * NC] = conv1_w[tid + i * NC];
    __syncthreads();

    float acc[MIP];
#pragma unroll
    for (int m = 0; m < MIP; m++) acc[m] = 0.f;

    const float* sp = g_s + (size_t)b * NC * 128 + (size_t)(cg * 32) * 128 + lg * 32 + l;
#pragma unroll 8
    for (int cc = 0; cc < 32; cc++) {
        const float v = sp[cc * 128];
#pragma unroll
        for (int m = 0; m < MIP; m++) acc[m] += w1s[m * NC + cg * 32 + cc] * v;
    }
#pragma unroll
    for (int m = 0; m < MIP; m++) part[cg][m * 32 + l] = acc[m];
    __syncthreads();

    {
        float s = 0.f;
#pragma unroll
        for (int g = 0; g < 8; g++) s += part[g][tid];
        const int m = tid >> 5;
        const float scale = bn1_g[m] * rsqrtf(bn1_v[m] + EPS);
        const float val   = (s - bn1_m[m]) * scale + bn1_b[m];
        g_y[(size_t)b * (MIP * 128) + m * 128 + lg * 32 + (tid & 31)] =
            val * fminf(fmaxf(val + 3.f, 0.f), 6.f) * (1.f / 6.f);
    }
}

// ---------------------------------------------------------------------------
// Kernel 3 (fused): attention + stream via TMA.
//   - issue cp.async.bulk (16 KB x-slice -> smem) from one thread
//   - attention prologue (independent of x) runs WHILE the TMA is in flight
//   - wait mbarrier, multiply from smem, streaming store.
// Reverse bc order preserves the L2-tail trick.
// ---------------------------------------------------------------------------
__global__ __launch_bounds__(256) void k_apply(
    const float* __restrict__ x,
    const float* __restrict__ convh_w, const float* __restrict__ convw_w,
    float* __restrict__ out)
{
    __shared__ __align__(128) float tile[NH * NW];   // 16 KB
    __shared__ unsigned long long mbar;
    __shared__ __align__(16) float ah[64];
    __shared__ __align__(16) float aw[64];

    const int bc  = (NB * NC - 1) - blockIdx.x;
    const int b   = bc >> 8;
    const int c   = bc & 255;
    const int tid = threadIdx.x;

    const uint32_t mbar_a = (uint32_t)__cvta_generic_to_shared(&mbar);
    const uint32_t tile_a = (uint32_t)__cvta_generic_to_shared(tile);

    if (tid == 0) {
        asm volatile("mbarrier.init.shared.b64 [%0], 1;" :: "r"(mbar_a) : "memory");
    }
    __syncthreads();
    if (tid == 0) {
        asm volatile("mbarrier.arrive.expect_tx.shared.b64 _, [%0], %1;"
                     :: "r"(mbar_a), "r"(16384u) : "memory");
        asm volatile(
            "cp.async.bulk.shared::cta.global.mbarrier::complete_tx::bytes "
            "[%0], [%1], %2, [%3];"
            :: "r"(tile_a), "l"(x + (size_t)bc * (NH * NW)), "r"(16384u), "r"(mbar_a)
            : "memory");
    }

    // Attention prologue overlaps the TMA flight (independent of x).
    if (tid < 128) {
        const int l   = tid & 63;
        const int off = (tid < 64) ? 0 : 64;
        const float* yb = g_y + (size_t)b * (MIP * 128) + off + l;
        const float* wp = ((tid < 64) ? convh_w : convw_w) + c * MIP;
        float s = 0.f;
#pragma unroll
        for (int m = 0; m < MIP; m++) s += wp[m] * __ldg(&yb[m * 128]);
        const float a = 1.f / (1.f + __expf(-s));
        ((tid < 64) ? ah : aw)[l] = a;
    }
    __syncthreads();   // ah/aw visible to all threads

    // Wait for the x tile.
    {
        uint32_t done = 0;
        while (!done) {
            asm volatile(
                "{\n\t.reg .pred p;\n\t"
                "mbarrier.try_wait.parity.acquire.cta.shared::cta.b64 p, [%1], 0;\n\t"
                "selp.b32 %0, 1, 0, p;\n\t}"
                : "=r"(done) : "r"(mbar_a) : "memory");
        }
    }

    const float4* t4 = (const float4*)tile;
    float4*       o4 = (float4*)(out + (size_t)bc * (NH * NW));
#pragma unroll
    for (int i = 0; i < 4; i++) {
        const int f  = tid + i * 256;    // 0..1023
        const int h  = f >> 4;           // 0..63
        const int w4 = f & 15;           // 0..15
        const float4 xv = t4[f];
        const float  a1 = ah[h];
        const float4 a2 = ((const float4*)aw)[w4];
        float4 o;
        o.x = xv.x * a1 * a2.x;
        o.y = xv.y * a1 * a2.y;
        o.z = xv.z * a1 * a2.z;
        o.w = xv.w * a1 * a2.w;
        __stcs(&o4[f], o);               // streaming store: evict-first in L2
    }
}

// ---------------------------------------------------------------------------
extern "C" void kernel_launch(void* const* d_in, const int* in_sizes, int n_in,
                              void* d_out, int out_size)
{
    const float* x       = (const float*)d_in[0];
    const float* sph_w3  = (const float*)d_in[1];
    const float* sph_w7  = (const float*)d_in[2];
    const float* sph_g   = (const float*)d_in[3];
    const float* sph_b   = (const float*)d_in[4];
    const float* sph_m   = (const float*)d_in[5];
    const float* sph_v   = (const float*)d_in[6];
    const float* spw_w3  = (const float*)d_in[7];
    const float* spw_w7  = (const float*)d_in[8];
    const float* spw_g   = (const float*)d_in[9];
    const float* spw_b   = (const float*)d_in[10];
    const float* spw_m   = (const float*)d_in[11];
    const float* spw_v   = (const float*)d_in[12];
    const float* conv1_w = (const float*)d_in[13];
    const float* bn1_g   = (const float*)d_in[14];
    const float* bn1_b   = (const float*)d_in[15];
    const float* bn1_m   = (const float*)d_in[16];
    const float* bn1_v   = (const float*)d_in[17];
    const float* convh_w = (const float*)d_in[18];
    const float* convw_w = (const float*)d_in[19];
    float* out = (float*)d_out;

    k_reduce_strip<<<NB * NC, 128>>>(x,
        sph_w3, sph_w7, sph_g, sph_b, sph_m, sph_v,
        spw_w3, spw_w7, spw_g, spw_b, spw_m, spw_v);

    k_y<<<NB * 4, 256>>>(conv1_w, bn1_g, bn1_b, bn1_m, bn1_v);

    k_apply<<<NB * NC, 256>>>(x, convh_w, convw_w, out);
}